// round 16
// baseline (speedup 1.0000x reference)
#include <cuda_runtime.h>
#include <math.h>
#include <stdint.h>

#define NN 4096
#define NF 4096
#define NH 4
#define ALPHA 0.2f
#define L2E 1.4426950408889634f
typedef unsigned long long ull;
typedef unsigned int u32;

// Scratch (no allocations allowed)
__device__ float g_Wh[NN * 32];      // row-major [n][c], c = h*8+o
__device__ float g_ss[NH * NN];      // s_src, pre-scaled by log2(e)
__device__ float g_sd[NH * NN];      // s_dst, pre-scaled by log2(e)
__device__ float g_smax[NH];         // global max of scaled s_dst per head
__device__ float g_Dex[NH * NN * 2]; // interleaved (2^sd, 2^(ALPHA*sd)) per (h,j)

__device__ __forceinline__ ull pack2(float x) { ull r; asm("mov.b64 %0,{%1,%1};" : "=l"(r) : "f"(x)); return r; }
__device__ __forceinline__ void fma2(ull& acc, ull a, ull b) { asm("fma.rn.f32x2 %0,%1,%2,%0;" : "+l"(acc) : "l"(a), "l"(b)); }
__device__ __forceinline__ ull add2(ull a, ull b) { ull r; asm("add.rn.f32x2 %0,%1,%2;" : "=l"(r) : "l"(a), "l"(b)); return r; }
__device__ __forceinline__ void unpack2(ull a, float& x, float& y) { asm("mov.b64 {%0,%1},%2;" : "=f"(x), "=f"(y) : "l"(a)); }
__device__ __forceinline__ float ex2f(float x) { float r; asm("ex2.approx.f32 %0,%1;" : "=f"(r) : "f"(x)); return r; }
__device__ __forceinline__ void cpa16(u32 dst, const void* src) {
    asm volatile("cp.async.cg.shared.global [%0], [%1], 16;" :: "r"(dst), "l"(src));
}
#define CP_COMMIT() asm volatile("cp.async.commit_group;" ::: "memory")
#define CP_WAIT1()  asm volatile("cp.async.wait_group 1;" ::: "memory")
#define CP_WAIT0()  asm volatile("cp.async.wait_group 0;" ::: "memory")

// ---------------- K1: Wh = x @ W (8 rows/block, 3 blocks/SM, cp.async 3-stage) ----------------
#define R1 8
__global__ __launch_bounds__(256, 3) void k1_gemm(
    const float* __restrict__ x, const float* __restrict__ W, const float* __restrict__ a)
{
    __shared__ float sW3[3][128 * 32];    // [k][c], dense LDS.128 pattern   48 KB
    __shared__ float sx3[3][R1 * 132];    // [r][k] padded                   12.4 KB
    __shared__ float sP[8 * R1 * 33];     // cross-warp partials              8.25 KB
    const int tid = threadIdx.x;
    const int w = tid >> 5, lane = tid & 31;
    const int ks = lane >> 3, q = lane & 7;
    const int i0 = blockIdx.x * R1;

    const u32 bW = (u32)__cvta_generic_to_shared(&sW3[0][0]);
    const u32 bX = (u32)__cvta_generic_to_shared(&sx3[0][0]);

    ull acc[R1][2];
    #pragma unroll
    for (int r = 0; r < R1; r++) { acc[r][0] = 0ULL; acc[r][1] = 0ULL; }

    auto stage = [&](int buf, int k0) {
        #pragma unroll
        for (int it = 0; it < 4; it++) {
            int idx = tid + it * 256; int kk = idx >> 3, c4 = idx & 7;
            cpa16(bW + (u32)(buf * 4096 + kk * 32 + c4 * 4) * 4,
                  W + (size_t)(c4 >> 1) * NF * 8 + (size_t)(k0 + kk) * 8 + (c4 & 1) * 4);
        }
        {   // 8 rows x 128 k = 256 float4, exactly one per thread
            int r = tid >> 5, k4 = tid & 31;
            cpa16(bX + (u32)(buf * (R1 * 132) + r * 132 + k4 * 4) * 4,
                  x + (size_t)(i0 + r) * NF + k0 + k4 * 4);
        }
    };

    stage(0, 0);   CP_COMMIT();
    stage(1, 128); CP_COMMIT();

    int buf = 0;
    for (int c = 0; c < 32; c++) {
        if (c < 31) { CP_WAIT1(); } else { CP_WAIT0(); }
        __syncthreads();
        if (c < 30) {
            int nb = buf + 2; if (nb >= 3) nb -= 3;
            stage(nb, (c + 2) * 128);
            CP_COMMIT();
        }
        const float* sWb = &sW3[buf][0];
        const float* sxb = &sx3[buf][0];
        const int base = w * 16;
        #pragma unroll
        for (int kk = 0; kk < 2; kk++) {
            const int kl = base + kk * 8 + ks * 2;
            ulonglong2 wA = *(const ulonglong2*)(sWb + kl * 32 + q * 4);        // dense LDS.128
            ulonglong2 wB = *(const ulonglong2*)(sWb + (kl + 1) * 32 + q * 4);  // dense LDS.128
            #pragma unroll
            for (int r = 0; r < R1; r++) {
                ull px = *(const ull*)(sxb + r * 132 + kl);    // 1-phase LDS.64 (k-pair)
                float xa, xb; unpack2(px, xa, xb);
                ull da = pack2(xa), db = pack2(xb);
                fma2(acc[r][0], wA.x, da); fma2(acc[r][1], wA.y, da);
                fma2(acc[r][0], wB.x, db); fma2(acc[r][1], wB.y, db);
            }
        }
        if (++buf >= 3) buf = 0;
    }

    #pragma unroll
    for (int r = 0; r < R1; r++) {
        #pragma unroll
        for (int p = 0; p < 2; p++) {
            acc[r][p] = add2(acc[r][p], __shfl_xor_sync(0xffffffffu, acc[r][p], 8));
            acc[r][p] = add2(acc[r][p], __shfl_xor_sync(0xffffffffu, acc[r][p], 16));
        }
    }
    if (ks == 0) {
        #pragma unroll
        for (int r = 0; r < R1; r++) {
            float f0, f1, f2, f3;
            unpack2(acc[r][0], f0, f1); unpack2(acc[r][1], f2, f3);
            float* d = sP + w * (R1 * 33) + r * 33 + q * 4;
            d[0] = f0; d[1] = f1; d[2] = f2; d[3] = f3;
        }
    }
    __syncthreads();
    {   // cross-warp sum: 256 threads = 8 rows x 32 cols
        int cc = tid & 31, r = tid >> 5;
        float v = 0.f;
        #pragma unroll
        for (int w8 = 0; w8 < 8; w8++) v += sP[w8 * (R1 * 33) + r * 33 + cc];
        g_Wh[(size_t)(i0 + r) * 32 + cc] = v;
        sx3[0][r * 33 + cc] = v;    // stash for epilogue (after barrier, safe)
    }
    __syncthreads();
    if (tid < 32) {
        int r = tid >> 2, h = tid & 3;
        const float* ev = &sx3[0][r * 33 + h * 8];
        const float* ah = a + h * 16;
        float ss = 0.f, sd = 0.f;
        #pragma unroll
        for (int o = 0; o < 8; o++) { float v = ev[o]; ss += v * ah[o]; sd += v * ah[8 + o]; }
        g_ss[h * NN + i0 + r] = ss * L2E;
        g_sd[h * NN + i0 + r] = sd * L2E;
    }
}

// ---------------- K_prep: per-head smax + exp factors + out init (merged) ----------------
__global__ void k_prep(const float* __restrict__ b_lin, float* __restrict__ dout)
{
    __shared__ float sm[256];
    const int h = blockIdx.x, tid = threadIdx.x;
    if (h == 0 && tid < 8) dout[tid] = b_lin[0];
    float m = -1e30f;
    for (int j = tid; j < NN; j += 256) {
        float sd = g_sd[h * NN + j];
        m = fmaxf(m, sd);
        g_Dex[(h * NN + j) * 2 + 0] = ex2f(sd);
        g_Dex[(h * NN + j) * 2 + 1] = ex2f(ALPHA * sd);
    }
    sm[tid] = m;
    __syncthreads();
    for (int s2 = 128; s2 > 0; s2 >>= 1) {
        if (tid < s2) sm[tid] = fmaxf(sm[tid], sm[tid + s2]);
        __syncthreads();
    }
    if (tid == 0) g_smax[h] = sm[0];
}

// ---------------- K2: masked softmax attention (cp.async double-buffered, factorized exp) ----------------
// block 256 = 8 warps; warp = (rq 0..1) x (head h 0..3): 4 rows, 1 head per warp.
#define R2B 8
__global__ __launch_bounds__(256, 3) void k2_attn(
    const int* __restrict__ adj, const float* __restrict__ w_lin, float* __restrict__ dout)
{
    __shared__ float sWh[2][128 * 36];   // [j][c] (+pad): dense LDS.128
    __shared__ float sDx[2][4 * 264];    // [h][j] float2 (D, D2)
    __shared__ int   sAdj[2][8 * 128];   // [r][j]
    __shared__ float sRed[R2B][4][8];
    const int tid = threadIdx.x, lane = tid & 31;
    const int w = tid >> 5;
    const int h = w & 3, rq = w >> 2;
    const int i0 = blockIdx.x * R2B;
    const int rbase = i0 + rq * 4;

    const u32 bWh  = (u32)__cvta_generic_to_shared(&sWh[0][0]);
    const u32 bDx  = (u32)__cvta_generic_to_shared(&sDx[0][0]);
    const u32 bAdj = (u32)__cvta_generic_to_shared(&sAdj[0][0]);
    const int* adjblk = adj + (size_t)i0 * NN;

    float EA[4], EA2[4], l[4];
    ull acc2[4][4];
    #pragma unroll
    for (int rr = 0; rr < 4; rr++) {
        float ss = g_ss[h * NN + rbase + rr];
        float t = ss + g_smax[h];
        float M = fmaxf(t, ALPHA * t);
        EA[rr]  = ex2f(ss - M);
        EA2[rr] = ex2f(ALPHA * ss - M);
        l[rr] = 0.f;
        #pragma unroll
        for (int q = 0; q < 4; q++) acc2[rr][q] = 0ULL;
    }

    auto stage = [&](int buf, int j0) {
        #pragma unroll
        for (int it = 0; it < 4; it++) {
            int idx = tid + it * 256;
            int jj = idx >> 3, q = idx & 7;
            cpa16(bWh + (u32)(buf * (128 * 36) + jj * 36 + q * 4) * 4,
                  g_Wh + (size_t)(j0 + jj) * 32 + q * 4);
        }
        {
            int hh = tid >> 6, jj2 = tid & 63;
            cpa16(bDx + (u32)(buf * (4 * 264) + hh * 264 + jj2 * 4) * 4,
                  g_Dex + ((size_t)hh * NN + j0 + jj2 * 2) * 2);
        }
        {
            int r = tid >> 5, j4 = tid & 31;
            cpa16(bAdj + (u32)(buf * (8 * 128) + r * 128 + j4 * 4) * 4,
                  adjblk + (size_t)r * NN + j0 + j4 * 4);
        }
    };

    stage(0, 0);
    CP_COMMIT();

    for (int t = 0; t < 32; t++) {
        const int cur = t & 1;
        if (t < 31) {
            stage((t + 1) & 1, (t + 1) * 128);
            CP_COMMIT();
            CP_WAIT1();
        } else {
            CP_WAIT0();
        }
        __syncthreads();

        #pragma unroll
        for (int js = 0; js < 4; js++) {
            const int j = js * 32 + lane;
            float2 dx = *(const float2*)(&sDx[cur][h * 264 + j * 2]);   // dense LDS.64
            const float* whb = &sWh[cur][j * 36 + h * 8];
            ulonglong2 w01 = *(const ulonglong2*)(whb);      // dense LDS.128
            ulonglong2 w23 = *(const ulonglong2*)(whb + 4);  // dense LDS.128
            #pragma unroll
            for (int rr = 0; rr < 4; rr++) {
                int av = sAdj[cur][(rq * 4 + rr) * 128 + j]; // dense LDS.32, av in {0,1}
                float wgt = fmaxf(EA[rr] * dx.x, EA2[rr] * dx.y);  // = 2^(lrelu(ss+sd)-M)
                wgt = __int_as_float(__float_as_int(wgt) & (-av)); // branchless mask
                l[rr] += wgt;
                ull p = pack2(wgt);
                fma2(acc2[rr][0], w01.x, p); fma2(acc2[rr][1], w01.y, p);
                fma2(acc2[rr][2], w23.x, p); fma2(acc2[rr][3], w23.y, p);
            }
        }
        __syncthreads();
    }

    #pragma unroll
    for (int off = 16; off >= 1; off >>= 1) {
        #pragma unroll
        for (int rr = 0; rr < 4; rr++) {
            #pragma unroll
            for (int q = 0; q < 4; q++)
                acc2[rr][q] = add2(acc2[rr][q], __shfl_xor_sync(0xffffffffu, acc2[rr][q], off));
            l[rr] += __shfl_xor_sync(0xffffffffu, l[rr], off);
        }
    }

    if (lane == 0) {
        #pragma unroll
        for (int rr = 0; rr < 4; rr++) {
            float inv = 1.f / l[rr];
            #pragma unroll
            for (int q = 0; q < 4; q++) {
                float x0, x1;
                unpack2(acc2[rr][q], x0, x1);
                sRed[rq * 4 + rr][h][q * 2 + 0] = x0 * inv;
                sRed[rq * 4 + rr][h][q * 2 + 1] = x1 * inv;
            }
        }
    }
    __syncthreads();

    if (tid < R2B) {
        const int row = i0 + tid;
        float emb[8], m = -1e30f;
        #pragma unroll
        for (int o = 0; o < 8; o++) {
            float v = 0.25f * (sRed[tid][0][o] + sRed[tid][1][o] + sRed[tid][2][o] + sRed[tid][3][o]);
            emb[o] = v; m = fmaxf(m, v);
            dout[8 + (size_t)row * 8 + o] = v;      // node_embeddings
        }
        float sum = 0.f;
        #pragma unroll
        for (int o = 0; o < 8; o++) sum += expf(emb[o] - m);
        float lg = logf(sum) + m;
        float wv = w_lin[row];
        #pragma unroll
        for (int o = 0; o < 8; o++) atomicAdd(&dout[o], (emb[o] - lg) * wv);
    }
}

extern "C" void kernel_launch(void* const* d_in, const int* in_sizes, int n_in,
                              void* d_out, int out_size)
{
    const float* x     = (const float*)d_in[0];
    const int*   adj   = (const int*)d_in[1];
    const float* W     = (const float*)d_in[2];
    const float* a     = (const float*)d_in[3];
    const float* w_lin = (const float*)d_in[4];
    const float* b_lin = (const float*)d_in[5];
    float* out = (float*)d_out;

    k1_gemm<<<NN / R1, 256>>>(x, W, a);
    k_prep<<<NH, 256>>>(b_lin, out);
    k2_attn<<<NN / R2B, 256>>>(adj, w_lin, out);
}

// round 17
// speedup vs baseline: 1.1302x; 1.1302x over previous
#include <cuda_runtime.h>
#include <math.h>
#include <stdint.h>

#define NN 4096
#define NF 4096
#define NH 4
#define ALPHA 0.2f
#define L2E 1.4426950408889634f
typedef unsigned long long ull;
typedef unsigned int u32;

// Scratch (no allocations allowed)
__device__ float g_Wh[NN * 32];      // row-major [n][c], c = h*8+o
__device__ float g_ss[NH * NN];      // s_src, pre-scaled by log2(e)
__device__ float g_sd[NH * NN];      // s_dst, pre-scaled by log2(e)
__device__ float g_smax[NH];         // global max of scaled s_dst per head
__device__ float g_Dex[NH * NN * 2]; // interleaved (2^sd, 2^(ALPHA*sd)) per (h,j)

__device__ __forceinline__ ull pack2(float x) { ull r; asm("mov.b64 %0,{%1,%1};" : "=l"(r) : "f"(x)); return r; }
__device__ __forceinline__ void fma2(ull& acc, ull a, ull b) { asm("fma.rn.f32x2 %0,%1,%2,%0;" : "+l"(acc) : "l"(a), "l"(b)); }
__device__ __forceinline__ ull add2(ull a, ull b) { ull r; asm("add.rn.f32x2 %0,%1,%2;" : "=l"(r) : "l"(a), "l"(b)); return r; }
__device__ __forceinline__ void unpack2(ull a, float& x, float& y) { asm("mov.b64 {%0,%1},%2;" : "=f"(x), "=f"(y) : "l"(a)); }
__device__ __forceinline__ float ex2f(float x) { float r; asm("ex2.approx.f32 %0,%1;" : "=f"(r) : "f"(x)); return r; }
__device__ __forceinline__ void cpa16(u32 dst, const void* src) {
    asm volatile("cp.async.cg.shared.global [%0], [%1], 16;" :: "r"(dst), "l"(src));
}
#define CP_COMMIT() asm volatile("cp.async.commit_group;" ::: "memory")
#define CP_WAIT1()  asm volatile("cp.async.wait_group 1;" ::: "memory")
#define CP_WAIT0()  asm volatile("cp.async.wait_group 0;" ::: "memory")

// ---------------- K1: Wh = x @ W (R14 config: 16 rows, k-pair LDS.64, cp.async 3-stage) ----------------
#define R1 16
__global__ __launch_bounds__(256, 2) void k1_gemm(
    const float* __restrict__ x, const float* __restrict__ W, const float* __restrict__ a)
{
    __shared__ float sW3[3][128 * 32];    // [k][c], dense LDS.128 pattern
    __shared__ float sx3[3][R1 * 132];    // [r][k] padded
    __shared__ float sP[8 * R1 * 33];     // cross-warp partials
    const int tid = threadIdx.x;
    const int w = tid >> 5, lane = tid & 31;
    const int ks = lane >> 3, q = lane & 7;
    const int i0 = blockIdx.x * R1;

    const u32 bW = (u32)__cvta_generic_to_shared(&sW3[0][0]);
    const u32 bX = (u32)__cvta_generic_to_shared(&sx3[0][0]);

    ull acc[R1][2];
    #pragma unroll
    for (int r = 0; r < R1; r++) { acc[r][0] = 0ULL; acc[r][1] = 0ULL; }

    auto stage = [&](int buf, int k0) {
        #pragma unroll
        for (int it = 0; it < 4; it++) {
            int idx = tid + it * 256; int kk = idx >> 3, c4 = idx & 7;
            cpa16(bW + (u32)(buf * 4096 + kk * 32 + c4 * 4) * 4,
                  W + (size_t)(c4 >> 1) * NF * 8 + (size_t)(k0 + kk) * 8 + (c4 & 1) * 4);
        }
        #pragma unroll
        for (int it = 0; it < 2; it++) {
            int idx = tid + it * 256; int r = idx >> 5, k4 = idx & 31;
            cpa16(bX + (u32)(buf * (R1 * 132) + r * 132 + k4 * 4) * 4,
                  x + (size_t)(i0 + r) * NF + k0 + k4 * 4);
        }
    };

    stage(0, 0);   CP_COMMIT();
    stage(1, 128); CP_COMMIT();

    int buf = 0;
    for (int c = 0; c < 32; c++) {
        if (c < 31) { CP_WAIT1(); } else { CP_WAIT0(); }
        __syncthreads();
        if (c < 30) {
            int nb = buf + 2; if (nb >= 3) nb -= 3;
            stage(nb, (c + 2) * 128);
            CP_COMMIT();
        }
        const float* sWb = &sW3[buf][0];
        const float* sxb = &sx3[buf][0];
        const int base = w * 16;
        #pragma unroll
        for (int kk = 0; kk < 2; kk++) {
            const int kl = base + kk * 8 + ks * 2;
            ulonglong2 wA = *(const ulonglong2*)(sWb + kl * 32 + q * 4);        // dense LDS.128
            ulonglong2 wB = *(const ulonglong2*)(sWb + (kl + 1) * 32 + q * 4);  // dense LDS.128
            #pragma unroll
            for (int r = 0; r < R1; r++) {
                ull px = *(const ull*)(sxb + r * 132 + kl);    // 1-phase LDS.64 (k-pair)
                float xa, xb; unpack2(px, xa, xb);
                ull da = pack2(xa), db = pack2(xb);
                fma2(acc[r][0], wA.x, da); fma2(acc[r][1], wA.y, da);
                fma2(acc[r][0], wB.x, db); fma2(acc[r][1], wB.y, db);
            }
        }
        if (++buf >= 3) buf = 0;
    }

    #pragma unroll
    for (int r = 0; r < R1; r++) {
        #pragma unroll
        for (int p = 0; p < 2; p++) {
            acc[r][p] = add2(acc[r][p], __shfl_xor_sync(0xffffffffu, acc[r][p], 8));
            acc[r][p] = add2(acc[r][p], __shfl_xor_sync(0xffffffffu, acc[r][p], 16));
        }
    }
    if (ks == 0) {
        #pragma unroll
        for (int r = 0; r < R1; r++) {
            float f0, f1, f2, f3;
            unpack2(acc[r][0], f0, f1); unpack2(acc[r][1], f2, f3);
            float* d = sP + w * (R1 * 33) + r * 33 + q * 4;
            d[0] = f0; d[1] = f1; d[2] = f2; d[3] = f3;
        }
    }
    __syncthreads();
    {
        int cc = tid & 31, rb = tid >> 5;
        #pragma unroll
        for (int rr = 0; rr < 2; rr++) {
            int r = rb + rr * 8;
            float v = 0.f;
            #pragma unroll
            for (int w8 = 0; w8 < 8; w8++) v += sP[w8 * (R1 * 33) + r * 33 + cc];
            g_Wh[(size_t)(i0 + r) * 32 + cc] = v;
            sx3[0][r * 33 + cc] = v;    // stash for epilogue (after barrier, safe)
        }
    }
    __syncthreads();
    if (tid < 64) {
        int r = tid >> 2, h = tid & 3;
        const float* ev = &sx3[0][r * 33 + h * 8];
        const float* ah = a + h * 16;
        float ss = 0.f, sd = 0.f;
        #pragma unroll
        for (int o = 0; o < 8; o++) { float v = ev[o]; ss += v * ah[o]; sd += v * ah[8 + o]; }
        g_ss[h * NN + i0 + r] = ss * L2E;
        g_sd[h * NN + i0 + r] = sd * L2E;
    }
}

// ---------------- K_prep: per-head smax + exp factors + out init (merged) ----------------
__global__ void k_prep(const float* __restrict__ b_lin, float* __restrict__ dout)
{
    __shared__ float sm[256];
    const int h = blockIdx.x, tid = threadIdx.x;
    if (h == 0 && tid < 8) dout[tid] = b_lin[0];
    float m = -1e30f;
    for (int j = tid; j < NN; j += 256) {
        float sd = g_sd[h * NN + j];
        m = fmaxf(m, sd);
        g_Dex[(h * NN + j) * 2 + 0] = ex2f(sd);
        g_Dex[(h * NN + j) * 2 + 1] = ex2f(ALPHA * sd);
    }
    sm[tid] = m;
    __syncthreads();
    for (int s2 = 128; s2 > 0; s2 >>= 1) {
        if (tid < s2) sm[tid] = fmaxf(sm[tid], sm[tid + s2]);
        __syncthreads();
    }
    if (tid == 0) g_smax[h] = sm[0];
}

// ---------------- K2: masked softmax attention (cp.async 3-stage, ONE barrier/tile) ----------------
// block 256 = 8 warps; warp = (rq 0..1) x (head h 0..3): 2 rows, 1 head per warp. 4 rows/block.
#define R2B 4
__global__ __launch_bounds__(256, 3) void k2_attn(
    const int* __restrict__ adj, const float* __restrict__ w_lin, float* __restrict__ dout)
{
    __shared__ float sWh[3][128 * 36];   // [j][c] (+pad): dense LDS.128   54 KB
    __shared__ float sDx[3][4 * 264];    // [h][j] float2 (D, D2)          12.7 KB
    __shared__ int   sAdj[3][4 * 128];   // [r][j]                          6.1 KB
    __shared__ float sRed[R2B][4][8];
    const int tid = threadIdx.x, lane = tid & 31;
    const int w = tid >> 5;
    const int h = w & 3, rq = w >> 2;
    const int i0 = blockIdx.x * R2B;
    const int rbase = i0 + rq * 2;

    const u32 bWh  = (u32)__cvta_generic_to_shared(&sWh[0][0]);
    const u32 bDx  = (u32)__cvta_generic_to_shared(&sDx[0][0]);
    const u32 bAdj = (u32)__cvta_generic_to_shared(&sAdj[0][0]);
    const int* adjblk = adj + (size_t)i0 * NN;

    float EA[2], EA2[2], l[2];
    ull acc2[2][4];
    #pragma unroll
    for (int rr = 0; rr < 2; rr++) {
        float ss = g_ss[h * NN + rbase + rr];
        float t = ss + g_smax[h];
        float M = fmaxf(t, ALPHA * t);
        EA[rr]  = ex2f(ss - M);
        EA2[rr] = ex2f(ALPHA * ss - M);
        l[rr] = 0.f;
        #pragma unroll
        for (int q = 0; q < 4; q++) acc2[rr][q] = 0ULL;
    }

    auto stage = [&](int buf, int j0) {
        #pragma unroll
        for (int it = 0; it < 4; it++) {
            int idx = tid + it * 256;
            int jj = idx >> 3, q = idx & 7;
            cpa16(bWh + (u32)(buf * (128 * 36) + jj * 36 + q * 4) * 4,
                  g_Wh + (size_t)(j0 + jj) * 32 + q * 4);
        }
        {
            int hh = tid >> 6, jj2 = tid & 63;
            cpa16(bDx + (u32)(buf * (4 * 264) + hh * 264 + jj2 * 4) * 4,
                  g_Dex + ((size_t)hh * NN + j0 + jj2 * 2) * 2);
        }
        if (tid < 128) {
            int r = tid >> 5, j4 = tid & 31;
            cpa16(bAdj + (u32)(buf * (4 * 128) + r * 128 + j4 * 4) * 4,
                  adjblk + (size_t)r * NN + j0 + j4 * 4);
        }
    };

    stage(0, 0);   CP_COMMIT();
    stage(1, 128); CP_COMMIT();

    int buf = 0;
    for (int t = 0; t < 32; t++) {
        if (t < 31) { CP_WAIT1(); } else { CP_WAIT0(); }
        __syncthreads();                 // single barrier per tile (3 buffers make it safe)
        if (t < 30) {
            int nb = buf + 2; if (nb >= 3) nb -= 3;
            stage(nb, (t + 2) * 128);
            CP_COMMIT();
        }

        #pragma unroll
        for (int js = 0; js < 4; js++) {
            const int j = js * 32 + lane;
            float2 dx = *(const float2*)(&sDx[buf][h * 264 + j * 2]);   // dense LDS.64
            const float* whb = &sWh[buf][j * 36 + h * 8];
            ulonglong2 w01 = *(const ulonglong2*)(whb);      // dense LDS.128
            ulonglong2 w23 = *(const ulonglong2*)(whb + 4);  // dense LDS.128
            #pragma unroll
            for (int rr = 0; rr < 2; rr++) {
                int av = sAdj[buf][(rq * 2 + rr) * 128 + j]; // dense LDS.32, av in {0,1}
                float wgt = fmaxf(EA[rr] * dx.x, EA2[rr] * dx.y);  // = 2^(lrelu(ss+sd)-M)
                wgt = __int_as_float(__float_as_int(wgt) & (-av)); // branchless mask
                l[rr] += wgt;
                ull p = pack2(wgt);
                fma2(acc2[rr][0], w01.x, p); fma2(acc2[rr][1], w01.y, p);
                fma2(acc2[rr][2], w23.x, p); fma2(acc2[rr][3], w23.y, p);
            }
        }
        if (++buf >= 3) buf = 0;
    }

    #pragma unroll
    for (int off = 16; off >= 1; off >>= 1) {
        #pragma unroll
        for (int rr = 0; rr < 2; rr++) {
            #pragma unroll
            for (int q = 0; q < 4; q++)
                acc2[rr][q] = add2(acc2[rr][q], __shfl_xor_sync(0xffffffffu, acc2[rr][q], off));
            l[rr] += __shfl_xor_sync(0xffffffffu, l[rr], off);
        }
    }

    if (lane == 0) {
        #pragma unroll
        for (int rr = 0; rr < 2; rr++) {
            float inv = 1.f / l[rr];
            #pragma unroll
            for (int q = 0; q < 4; q++) {
                float x0, x1;
                unpack2(acc2[rr][q], x0, x1);
                sRed[rq * 2 + rr][h][q * 2 + 0] = x0 * inv;
                sRed[rq * 2 + rr][h][q * 2 + 1] = x1 * inv;
            }
        }
    }
    __syncthreads();

    if (tid < R2B) {
        const int row = i0 + tid;
        float emb[8], m = -1e30f;
        #pragma unroll
        for (int o = 0; o < 8; o++) {
            float v = 0.25f * (sRed[tid][0][o] + sRed[tid][1][o] + sRed[tid][2][o] + sRed[tid][3][o]);
            emb[o] = v; m = fmaxf(m, v);
            dout[8 + (size_t)row * 8 + o] = v;      // node_embeddings
        }
        float sum = 0.f;
        #pragma unroll
        for (int o = 0; o < 8; o++) sum += expf(emb[o] - m);
        float lg = logf(sum) + m;
        float wv = w_lin[row];
        #pragma unroll
        for (int o = 0; o < 8; o++) atomicAdd(&dout[o], (emb[o] - lg) * wv);
    }
}

extern "C" void kernel_launch(void* const* d_in, const int* in_sizes, int n_in,
                              void* d_out, int out_size)
{
    const float* x     = (const float*)d_in[0];
    const int*   adj   = (const int*)d_in[1];
    const float* W     = (const float*)d_in[2];
    const float* a     = (const float*)d_in[3];
    const float* w_lin = (const float*)d_in[4];
    const float* b_lin = (const float*)d_in[5];
    float* out = (float*)d_out;

    k1_gemm<<<NN / R1, 256>>>(x, W, a);
    k_prep<<<NH, 256>>>(b_lin, out);
    k2_attn<<<NN / R2B, 256>>>(adj, w_lin, out);
}